// round 2
// baseline (speedup 1.0000x reference)
#include <cuda_runtime.h>
#include <cstdint>

#define NCH 8
#define HW 512
#define IMG (HW*HW)
#define CROP 506
#define CIMG (CROP*CROP)
#define NSHIFT 81

// 12 nonzero taps of the 13-tap half-pixel kernel, offsets -6..+5
__constant__ float c_w12[12] = {
    -1.20162964e-4f,  1.615524292e-3f, -1.0385513306e-2f,  4.3619155884e-2f,
    -1.45397186478e-1f, 6.1066818237e-1f, 6.1066818237e-1f, -1.45397186478e-1f,
     4.3619155884e-2f, -1.0385513306e-2f, 1.615524292e-3f, -1.20162964e-4f };

// device scratch (static: allocation is forbidden)
__device__ float g_tmp [NCH*IMG];
__device__ float g_p   [NCH*IMG];
__device__ float g_p2e [NCH*IMG];
__device__ float g_p2s [NCH*IMG];
__device__ float g_p2se[NCH*IMG];
__device__ float g_ap  [NCH*CIMG];
__device__ float g_sii [NCH*CIMG];
__device__ float g_kx  [NCH*41];
__device__ float g_ky  [NCH*41];
__device__ double g_rho[NSHIFT*NCH];

__global__ void k_zero() {
    int t = blockIdx.x*blockDim.x + threadIdx.x;
    if (t < NSHIFT*NCH) g_rho[t] = 0.0;
}

// exact separable factors of the rank-1 Gaussian MTF kernel
__global__ void k_sepfac(const float* __restrict__ K) {
    int c = blockIdx.x; int t = threadIdx.x;
    __shared__ float cm[41];
    __shared__ float tot;
    const float* Kc = K + c*1681;
    if (t < 41) { float s = 0.f; for (int y = 0; y < 41; ++y) s += Kc[y*41+t]; cm[t] = s; }
    __syncthreads();
    if (t == 0) { float s = 0.f; for (int i = 0; i < 41; ++i) s += cm[i]; tot = s; }
    __syncthreads();
    if (t < 41) {
        g_kx[c*41+t] = cm[t];
        float r = 0.f; for (int x = 0; x < 41; ++x) r += Kc[t*41+x];
        g_ky[c*41+t] = r / tot;
    }
}

// 41-tap horizontal Gaussian with edge clamp, 8 outputs/thread
__global__ void k_gaussH(const float* __restrict__ pan) {
    int i = blockIdx.x*blockDim.x + threadIdx.x;
    if (i >= NCH*512*64) return;
    int c = i >> 15; int rem = i & 32767;
    int y = rem >> 6; int x0 = (rem & 63) << 3;
    const float* row = pan + c*IMG + (y<<9);
    const float* w = g_kx + c*41;
    float v[48];
#pragma unroll
    for (int t = 0; t < 48; ++t) { int xx = x0 + t - 20; xx = min(511, max(0, xx)); v[t] = row[xx]; }
    float s[8];
#pragma unroll
    for (int j = 0; j < 8; ++j) s[j] = 0.f;
#pragma unroll
    for (int t = 0; t < 41; ++t) {
        float wt = w[t];
#pragma unroll
        for (int j = 0; j < 8; ++j) s[j] += wt * v[t+j];
    }
    float* o = g_tmp + c*IMG + (y<<9) + x0;
#pragma unroll
    for (int j = 0; j < 8; ++j) o[j] = s[j];
}

// 41-tap vertical Gaussian with edge clamp
__global__ void k_gaussV() {
    int i = blockIdx.x*blockDim.x + threadIdx.x;
    if (i >= NCH*512*64) return;
    int c = i >> 15; int rem = i & 32767;
    int yg = rem >> 9; int x = rem & 511;
    int y0 = yg << 3;
    const float* col = g_tmp + c*IMG + x;
    const float* w = g_ky + c*41;
    float v[48];
#pragma unroll
    for (int t = 0; t < 48; ++t) { int yy = y0 + t - 20; yy = min(511, max(0, yy)); v[t] = col[yy<<9]; }
    float s[8];
#pragma unroll
    for (int j = 0; j < 8; ++j) s[j] = 0.f;
#pragma unroll
    for (int t = 0; t < 41; ++t) {
        float wt = w[t];
#pragma unroll
        for (int j = 0; j < 8; ++j) s[j] += wt * v[t+j];
    }
    float* o = g_p + c*IMG + (y0<<9) + x;
#pragma unroll
    for (int j = 0; j < 8; ++j) o[j<<9] = s[j];
}

// 12-tap half-pixel filter, SAME zero-pad. which: 0 = g_p->g_p2e (H)
__global__ void k_c13h(int which) {
    const float* in = g_p; float* out = g_p2e; (void)which;
    int i = blockIdx.x*blockDim.x + threadIdx.x;
    if (i >= NCH*512*64) return;
    int c = i >> 15; int rem = i & 32767;
    int y = rem >> 6; int x0 = (rem & 63) << 3;
    const float* row = in + c*IMG + (y<<9);
    float v[19];
#pragma unroll
    for (int t = 0; t < 19; ++t) { int xx = x0 + t - 6; v[t] = ((unsigned)xx < 512u) ? row[xx] : 0.f; }
    float s[8];
#pragma unroll
    for (int j = 0; j < 8; ++j) s[j] = 0.f;
#pragma unroll
    for (int t = 0; t < 12; ++t) {
        float wt = c_w12[t];
#pragma unroll
        for (int j = 0; j < 8; ++j) s[j] += wt * v[t+j];
    }
    float* o = out + c*IMG + (y<<9) + x0;
#pragma unroll
    for (int j = 0; j < 8; ++j) o[j] = s[j];
}

// vertical variant. which: 0 = g_p->g_p2s, 1 = g_p2e->g_p2se
__global__ void k_c13v(int which) {
    const float* in = which ? g_p2e : g_p;
    float* out = which ? g_p2se : g_p2s;
    int i = blockIdx.x*blockDim.x + threadIdx.x;
    if (i >= NCH*512*64) return;
    int c = i >> 15; int rem = i & 32767;
    int yg = rem >> 9; int x = rem & 511;
    int y0 = yg << 3;
    const float* col = in + c*IMG + x;
    float v[19];
#pragma unroll
    for (int t = 0; t < 19; ++t) { int yy = y0 + t - 6; v[t] = ((unsigned)yy < 512u) ? col[yy<<9] : 0.f; }
    float s[8];
#pragma unroll
    for (int j = 0; j < 8; ++j) s[j] = 0.f;
#pragma unroll
    for (int t = 0; t < 12; ++t) {
        float wt = c_w12[t];
#pragma unroll
        for (int j = 0; j < 8; ++j) s[j] += wt * v[t+j];
    }
    float* o = out + c*IMG + (y0<<9) + x;
#pragma unroll
    for (int j = 0; j < 8; ++j) o[j<<9] = s[j];
}

// ms-side precompute: box window offsets -7..+8, zero pad outside 506x506
__global__ void k_ahsum(const float* __restrict__ ms) {
    int x = blockIdx.x*blockDim.x + threadIdx.x;
    if (x >= CROP) return;
    int y = blockIdx.y, c = blockIdx.z;
    const float* row = ms + c*IMG + (y+3)*512 + 3;
    float s = 0.f;
    for (int dx = -7; dx <= 8; ++dx) { int xx = x + dx; if ((unsigned)xx < (unsigned)CROP) s += row[xx]; }
    g_tmp[c*IMG + y*CROP + x] = s;
}
__global__ void k_aprime(const float* __restrict__ ms) {
    int x = blockIdx.x*blockDim.x + threadIdx.x;
    if (x >= CROP) return;
    int y = blockIdx.y, c = blockIdx.z;
    float s = 0.f;
    for (int dy = -7; dy <= 8; ++dy) { int yy = y + dy; if ((unsigned)yy < (unsigned)CROP) s += g_tmp[c*IMG + yy*CROP + x]; }
    float a = ms[c*IMG + (y+3)*512 + (x+3)];
    g_ap[c*CIMG + y*CROP + x] = a - s * (1.0f/256.0f);
}
__global__ void k_sqh() {
    int x = blockIdx.x*blockDim.x + threadIdx.x;
    if (x >= CROP) return;
    int y = blockIdx.y, c = blockIdx.z;
    const float* row = g_ap + c*CIMG + y*CROP;
    float s = 0.f;
    for (int dx = -7; dx <= 8; ++dx) { int xx = x + dx; if ((unsigned)xx < (unsigned)CROP) { float v = row[xx]; s += v*v; } }
    g_tmp[c*IMG + y*CROP + x] = s;
}
__global__ void k_sii() {
    int x = blockIdx.x*blockDim.x + threadIdx.x;
    if (x >= CROP) return;
    int y = blockIdx.y, c = blockIdx.z;
    float s = 0.f;
    for (int dy = -7; dy <= 8; ++dy) { int yy = y + dy; if ((unsigned)yy < (unsigned)CROP) s += g_tmp[c*IMG + yy*CROP + x]; }
    g_sii[c*CIMG + y*CROP + x] = fmaxf(s, 1e-20f);
}

// ---------------- fused rho kernel: one CTA = (shift, channel, 64x64 tile) ----------------
#define BSTR 95
#define HSTR 81
#define PSTR 81
#define QSTR 65
#define SMEM_FLOATS (94*BSTR + 94*HSTR + 79*PSTR + 79*PSTR)

__global__ void __launch_bounds__(512, 1)
k_rho()
{
    extern __shared__ float sm[];
    float* sb  = sm;                    // 94x94 b tile (stride 95)
    float* hb  = sb  + 94*BSTR;         // 94x79 horizontal 16-sums of b
    float* sbp = hb  + 94*HSTR;         // 79x79 b'
    float* sa  = sbp + 79*PSTR;         // 79x79 a'
    float* h2  = sb;                    // overlay: 79x64 hsum(b'^2)
    float* h3  = hb;                    // overlay: 79x64 hsum(a'b')
    float* red = sa;                    // overlay: reduction scratch

    const int z = blockIdx.z;
    const int s = z >> 3, c = z & 7;
    const int mi = s / 9, ni = s - mi*9;
    const int ri = (mi >> 1) - 2, ci = (ni >> 1) - 2;      // floor((m)/2)
    const int pk = ((mi & 1) << 1) | (ni & 1);
    const float* p2k = (pk == 0) ? g_p : (pk == 1) ? g_p2e : (pk == 2) ? g_p2s : g_p2se;
    const int y0 = (int)(blockIdx.y) << 6, x0 = (int)(blockIdx.x) << 6;
    const int tid = threadIdx.x;
    const int offy = 3 - ri, offx = 3 - ci;
    const float* p2c = p2k + c*IMG;
    const float* apc = g_ap + c*CIMG;

    // phase 0: load b (zero outside crop) and a'
    for (int k = tid; k < 94*94; k += 512) {
        int i = k / 94, j = k - i*94;
        int gy = y0 - 14 + i, gx = x0 - 14 + j;
        float v = 0.f;
        if ((unsigned)gy < (unsigned)CROP && (unsigned)gx < (unsigned)CROP)
            v = p2c[(gy + offy)*512 + (gx + offx)];
        sb[i*BSTR + j] = v;
    }
    for (int k = tid; k < 79*79; k += 512) {
        int i = k / 79, j = k - i*79;
        int gy = y0 - 7 + i, gx = x0 - 7 + j;
        sa[i*PSTR + j] = ((unsigned)gy < (unsigned)CROP && (unsigned)gx < (unsigned)CROP)
                         ? apc[gy*CROP + gx] : 0.f;
    }
    __syncthreads();

    // phase 1: horizontal 16-sums of b -> hb[94][79], sliding windows
    if (tid < 94*4) {
        int i = tid >> 2, ch = tid & 3;
        int u0 = ch*20, u1 = min(u0 + 20, 79);
        const float* r = sb + i*BSTR;
        float ssum = 0.f;
#pragma unroll
        for (int t = 0; t < 16; ++t) ssum += r[u0 + t];
        float* hrow = hb + i*HSTR;
        hrow[u0] = ssum;
        for (int u = u0 + 1; u < u1; ++u) { ssum += r[u+15] - r[u-1]; hrow[u] = ssum; }
    }
    __syncthreads();

    // phase 2: b' = b - box16(b)/256 on 79x79 (zero outside crop)
    if (tid < 79*6) {
        int u = tid % 79, seg = tid / 79;
        int v0 = seg*14, v1 = min(v0 + 14, 79);
        float ssum = 0.f;
#pragma unroll
        for (int t = 0; t < 16; ++t) ssum += hb[(v0 + t)*HSTR + u];
        for (int v = v0; v < v1; ++v) {
            if (v > v0) ssum += hb[(v+15)*HSTR + u] - hb[(v-1)*HSTR + u];
            float bp = 0.f;
            int gy = y0 - 7 + v, gx = x0 - 7 + u;
            if ((unsigned)gy < (unsigned)CROP && (unsigned)gx < (unsigned)CROP)
                bp = sb[(v+7)*BSTR + (u+7)] - ssum * (1.0f/256.0f);
            sbp[v*PSTR + u] = bp;
        }
    }
    __syncthreads();

    // phase 3: horizontal 16-sums of b'^2 and a'b' over 79 rows x 64 cols
    if (tid < 79*4) {
        int v = tid >> 2, ch = tid & 3;
        int q0 = ch << 4;
        const float* bpr = sbp + v*PSTR;
        const float* ar  = sa  + v*PSTR;
        float s2 = 0.f, s3 = 0.f;
#pragma unroll
        for (int t = 0; t < 16; ++t) { float b_ = bpr[q0+t], a_ = ar[q0+t]; s2 += b_*b_; s3 += a_*b_; }
        float* h2r = h2 + v*QSTR; float* h3r = h3 + v*QSTR;
        h2r[q0] = s2; h3r[q0] = s3;
        for (int q = q0 + 1; q < q0 + 16; ++q) {
            float nb = bpr[q+15], ob = bpr[q-1];
            float na = ar[q+15],  oa = ar[q-1];
            s2 += nb*nb - ob*ob;
            s3 += na*nb - oa*ob;
            h2r[q] = s2; h3r[q] = s3;
        }
    }
    __syncthreads();

    // phase 4: vertical 16-sums -> sjj, sij; accumulate rho
    float acc = 0.f;
    {
        int q = tid & 63, seg = tid >> 6;
        int pp0 = seg << 3;
        float s2 = 0.f, s3 = 0.f;
#pragma unroll
        for (int t = 0; t < 16; ++t) { s2 += h2[(pp0+t)*QSTR + q]; s3 += h3[(pp0+t)*QSTR + q]; }
        const float* siic = g_sii + c*CIMG;
        for (int p = pp0; p < pp0 + 8; ++p) {
            if (p > pp0) {
                s2 += h2[(p+15)*QSTR + q] - h2[(p-1)*QSTR + q];
                s3 += h3[(p+15)*QSTR + q] - h3[(p-1)*QSTR + q];
            }
            int gy = y0 + p, gx = x0 + q;
            if (gy < CROP && gx < CROP) {
                float sjj = fmaxf(s2, 1e-20f);
                float den = sqrtf(siic[gy*CROP + gx] * sjj) + 1e-20f;
                acc += __fdividef(s3, den);
            }
        }
    }
#pragma unroll
    for (int o = 16; o > 0; o >>= 1) acc += __shfl_down_sync(0xffffffffu, acc, o);
    if ((tid & 31) == 0) red[tid >> 5] = acc;
    __syncthreads();
    if (tid < 16) {
        float v = red[tid];
#pragma unroll
        for (int o = 8; o > 0; o >>= 1) v += __shfl_down_sync(0xffffu, v, o, 16);
        if (tid == 0) atomicAdd(&g_rho[z], (double)v);
    }
}

__global__ void k_argmax(int* __restrict__ out) {
    int c = threadIdx.x;
    if (c >= NCH) return;
    double best = -1e300; int bi = 0;
    for (int s = 0; s < NSHIFT; ++s) {
        double v = g_rho[s*NCH + c];
        if (v > best) { best = v; bi = s; }
    }
    out[c]       = bi / 9 - 4;
    out[NCH + c] = bi % 9 - 4;
}

extern "C" void kernel_launch(void* const* d_in, const int* in_sizes, int n_in,
                              void* d_out, int out_size) {
    const float* ms  = (const float*)d_in[0];
    const float* pan = (const float*)d_in[1];
    const float* mtf = (const float*)d_in[2];
    int* out = (int*)d_out;
    (void)in_sizes; (void)n_in; (void)out_size;

    cudaFuncSetAttribute(k_rho, cudaFuncAttributeMaxDynamicSharedMemorySize,
                         SMEM_FLOATS * (int)sizeof(float));

    k_zero<<<1, 656>>>();
    k_sepfac<<<NCH, 64>>>(mtf);
    k_gaussH<<<1024, 256>>>(pan);
    k_gaussV<<<1024, 256>>>();
    k_c13h<<<1024, 256>>>(0);
    k_c13v<<<1024, 256>>>(0);
    k_c13v<<<1024, 256>>>(1);

    dim3 mb(128), mg((CROP + 127)/128, CROP, NCH);
    k_ahsum <<<mg, mb>>>(ms);
    k_aprime<<<mg, mb>>>(ms);
    k_sqh   <<<mg, mb>>>();
    k_sii   <<<mg, mb>>>();

    k_rho<<<dim3(8, 8, NSHIFT*NCH), 512, SMEM_FLOATS * (int)sizeof(float)>>>();
    k_argmax<<<1, 32>>>(out);
}

// round 4
// speedup vs baseline: 1.4396x; 1.4396x over previous
#include <cuda_runtime.h>
#include <cstdint>

#define NCH 8
#define HW 512
#define IMG (HW*HW)
#define CROP 506
#define CIMG (CROP*CROP)
#define NSHIFT 81

// 12 nonzero taps of the 13-tap half-pixel kernel, offsets -6..+5
__constant__ float c_w12[12] = {
    -1.20162964e-4f,  1.615524292e-3f, -1.0385513306e-2f,  4.3619155884e-2f,
    -1.45397186478e-1f, 6.1066818237e-1f, 6.1066818237e-1f, -1.45397186478e-1f,
     4.3619155884e-2f, -1.0385513306e-2f, 1.615524292e-3f, -1.20162964e-4f };

// device scratch (static: allocation is forbidden)
__device__ float g_tmp [NCH*IMG];
__device__ float g_p   [NCH*IMG];
__device__ float g_p2e [NCH*IMG];
__device__ float g_p2s [NCH*IMG];
__device__ float g_p2se[NCH*IMG];
__device__ float g_ap  [NCH*CIMG];
__device__ float g_sii [NCH*CIMG];
__device__ float g_kx  [NCH*41];
__device__ float g_ky  [NCH*41];
__device__ double g_rho[NSHIFT*NCH];

__global__ void k_zero() {
    int t = blockIdx.x*blockDim.x + threadIdx.x;
    if (t < NSHIFT*NCH) g_rho[t] = 0.0;
}

// exact separable factors of the rank-1 Gaussian MTF kernel
__global__ void k_sepfac(const float* __restrict__ K) {
    int c = blockIdx.x; int t = threadIdx.x;
    __shared__ float cm[41];
    __shared__ float tot;
    const float* Kc = K + c*1681;
    if (t < 41) { float s = 0.f; for (int y = 0; y < 41; ++y) s += Kc[y*41+t]; cm[t] = s; }
    __syncthreads();
    if (t == 0) { float s = 0.f; for (int i = 0; i < 41; ++i) s += cm[i]; tot = s; }
    __syncthreads();
    if (t < 41) {
        g_kx[c*41+t] = cm[t];
        float r = 0.f; for (int x = 0; x < 41; ++x) r += Kc[t*41+x];
        g_ky[c*41+t] = r / tot;
    }
}

// 41-tap horizontal Gaussian with edge clamp, 8 outputs/thread
__global__ void k_gaussH(const float* __restrict__ pan) {
    int i = blockIdx.x*blockDim.x + threadIdx.x;
    if (i >= NCH*512*64) return;
    int c = i >> 15; int rem = i & 32767;
    int y = rem >> 6; int x0 = (rem & 63) << 3;
    const float* row = pan + c*IMG + (y<<9);
    const float* w = g_kx + c*41;
    float v[48];
#pragma unroll
    for (int t = 0; t < 48; ++t) { int xx = x0 + t - 20; xx = min(511, max(0, xx)); v[t] = row[xx]; }
    float s[8];
#pragma unroll
    for (int j = 0; j < 8; ++j) s[j] = 0.f;
#pragma unroll
    for (int t = 0; t < 41; ++t) {
        float wt = w[t];
#pragma unroll
        for (int j = 0; j < 8; ++j) s[j] += wt * v[t+j];
    }
    float* o = g_tmp + c*IMG + (y<<9) + x0;
#pragma unroll
    for (int j = 0; j < 8; ++j) o[j] = s[j];
}

// 41-tap vertical Gaussian with edge clamp
__global__ void k_gaussV() {
    int i = blockIdx.x*blockDim.x + threadIdx.x;
    if (i >= NCH*512*64) return;
    int c = i >> 15; int rem = i & 32767;
    int yg = rem >> 9; int x = rem & 511;
    int y0 = yg << 3;
    const float* col = g_tmp + c*IMG + x;
    const float* w = g_ky + c*41;
    float v[48];
#pragma unroll
    for (int t = 0; t < 48; ++t) { int yy = y0 + t - 20; yy = min(511, max(0, yy)); v[t] = col[yy<<9]; }
    float s[8];
#pragma unroll
    for (int j = 0; j < 8; ++j) s[j] = 0.f;
#pragma unroll
    for (int t = 0; t < 41; ++t) {
        float wt = w[t];
#pragma unroll
        for (int j = 0; j < 8; ++j) s[j] += wt * v[t+j];
    }
    float* o = g_p + c*IMG + (y0<<9) + x;
#pragma unroll
    for (int j = 0; j < 8; ++j) o[j<<9] = s[j];
}

// 12-tap half-pixel filter, SAME zero-pad, horizontal: g_p -> g_p2e
__global__ void k_c13h(int which) {
    const float* in = g_p; float* out = g_p2e; (void)which;
    int i = blockIdx.x*blockDim.x + threadIdx.x;
    if (i >= NCH*512*64) return;
    int c = i >> 15; int rem = i & 32767;
    int y = rem >> 6; int x0 = (rem & 63) << 3;
    const float* row = in + c*IMG + (y<<9);
    float v[19];
#pragma unroll
    for (int t = 0; t < 19; ++t) { int xx = x0 + t - 6; v[t] = ((unsigned)xx < 512u) ? row[xx] : 0.f; }
    float s[8];
#pragma unroll
    for (int j = 0; j < 8; ++j) s[j] = 0.f;
#pragma unroll
    for (int t = 0; t < 12; ++t) {
        float wt = c_w12[t];
#pragma unroll
        for (int j = 0; j < 8; ++j) s[j] += wt * v[t+j];
    }
    float* o = out + c*IMG + (y<<9) + x0;
#pragma unroll
    for (int j = 0; j < 8; ++j) o[j] = s[j];
}

// vertical variant. which: 0 = g_p->g_p2s, 1 = g_p2e->g_p2se
__global__ void k_c13v(int which) {
    const float* in = which ? g_p2e : g_p;
    float* out = which ? g_p2se : g_p2s;
    int i = blockIdx.x*blockDim.x + threadIdx.x;
    if (i >= NCH*512*64) return;
    int c = i >> 15; int rem = i & 32767;
    int yg = rem >> 9; int x = rem & 511;
    int y0 = yg << 3;
    const float* col = in + c*IMG + x;
    float v[19];
#pragma unroll
    for (int t = 0; t < 19; ++t) { int yy = y0 + t - 6; v[t] = ((unsigned)yy < 512u) ? col[yy<<9] : 0.f; }
    float s[8];
#pragma unroll
    for (int j = 0; j < 8; ++j) s[j] = 0.f;
#pragma unroll
    for (int t = 0; t < 12; ++t) {
        float wt = c_w12[t];
#pragma unroll
        for (int j = 0; j < 8; ++j) s[j] += wt * v[t+j];
    }
    float* o = out + c*IMG + (y0<<9) + x;
#pragma unroll
    for (int j = 0; j < 8; ++j) o[j<<9] = s[j];
}

// ms-side precompute: box window offsets -7..+8, zero pad outside 506x506
__global__ void k_ahsum(const float* __restrict__ ms) {
    int x = blockIdx.x*blockDim.x + threadIdx.x;
    if (x >= CROP) return;
    int y = blockIdx.y, c = blockIdx.z;
    const float* row = ms + c*IMG + (y+3)*512 + 3;
    float s = 0.f;
    for (int dx = -7; dx <= 8; ++dx) { int xx = x + dx; if ((unsigned)xx < (unsigned)CROP) s += row[xx]; }
    g_tmp[c*IMG + y*CROP + x] = s;
}
__global__ void k_aprime(const float* __restrict__ ms) {
    int x = blockIdx.x*blockDim.x + threadIdx.x;
    if (x >= CROP) return;
    int y = blockIdx.y, c = blockIdx.z;
    float s = 0.f;
    for (int dy = -7; dy <= 8; ++dy) { int yy = y + dy; if ((unsigned)yy < (unsigned)CROP) s += g_tmp[c*IMG + yy*CROP + x]; }
    float a = ms[c*IMG + (y+3)*512 + (x+3)];
    g_ap[c*CIMG + y*CROP + x] = a - s * (1.0f/256.0f);
}
__global__ void k_sqh() {
    int x = blockIdx.x*blockDim.x + threadIdx.x;
    if (x >= CROP) return;
    int y = blockIdx.y, c = blockIdx.z;
    const float* row = g_ap + c*CIMG + y*CROP;
    float s = 0.f;
    for (int dx = -7; dx <= 8; ++dx) { int xx = x + dx; if ((unsigned)xx < (unsigned)CROP) { float v = row[xx]; s += v*v; } }
    g_tmp[c*IMG + y*CROP + x] = s;
}
__global__ void k_sii() {
    int x = blockIdx.x*blockDim.x + threadIdx.x;
    if (x >= CROP) return;
    int y = blockIdx.y, c = blockIdx.z;
    float s = 0.f;
    for (int dy = -7; dy <= 8; ++dy) { int yy = y + dy; if ((unsigned)yy < (unsigned)CROP) s += g_tmp[c*IMG + yy*CROP + x]; }
    g_sii[c*CIMG + y*CROP + x] = fmaxf(s, 1e-20f);
}

// ---------------- fused rho kernel: one CTA = (shift, channel, 64x64 tile) ----------------
// smem layout (22943 floats = 91.8 KB -> 2 CTAs/SM):
//   A [0,8930):      sb 94x95 (b tile)           -> later sa 79x81 (a')
//   B [8930,16544):  hb 94x81 (hsum16 of b)      -> later h2 48x65 | h3 48x65 (half-tiles)
//   C [16544,22943): sbp 79x81 (b')              -> later red[16]
#define A_OFF 0
#define B_OFF 8930
#define C_OFF 16544
#define SMEM_FLOATS 22943
#define BSTR 95
#define HSTR 81
#define PSTR 81
#define QSTR 65

__global__ void __launch_bounds__(512, 2)
k_rho()
{
    extern __shared__ float sm[];
    float* sb  = sm + A_OFF;
    float* hb  = sm + B_OFF;
    float* sbp = sm + C_OFF;
    float* sa  = sm + A_OFF;            // overlay after phase 2
    float* h2  = sm + B_OFF;            // overlay: 48x65 per half
    float* h3  = sm + B_OFF + 48*QSTR;
    float* red = sm + C_OFF;            // overlay after final phase 3

    const int z = blockIdx.z;
    const int s = z >> 3, c = z & 7;
    const int mi = s / 9, ni = s - mi*9;
    const int ri = (mi >> 1) - 2, ci = (ni >> 1) - 2;
    const int pk = ((mi & 1) << 1) | (ni & 1);
    const float* p2k = (pk == 0) ? g_p : (pk == 1) ? g_p2e : (pk == 2) ? g_p2s : g_p2se;
    const int y0 = (int)(blockIdx.y) << 6, x0 = (int)(blockIdx.x) << 6;
    const int tid = threadIdx.x;
    const int offy = 3 - ri, offx = 3 - ci;
    const float* p2c = p2k + c*IMG;
    const float* apc = g_ap + c*CIMG;

    // phase 0: load b (zero outside crop)
    for (int k = tid; k < 94*94; k += 512) {
        int i = k / 94, j = k - i*94;
        int gy = y0 - 14 + i, gx = x0 - 14 + j;
        float v = 0.f;
        if ((unsigned)gy < (unsigned)CROP && (unsigned)gx < (unsigned)CROP)
            v = p2c[(gy + offy)*512 + (gx + offx)];
        sb[i*BSTR + j] = v;
    }
    __syncthreads();

    // phase 1: horizontal 16-sums of b -> hb[94][79]; 94x8 units (chunks of 10)
    for (int un = tid; un < 94*8; un += 512) {
        int i = un >> 3, ch = un & 7;
        int u0 = ch*10, u1 = min(u0 + 10, 79);
        const float* r = sb + i*BSTR;
        float ssum = 0.f;
#pragma unroll
        for (int t = 0; t < 16; ++t) ssum += r[u0 + t];
        float* hrow = hb + i*HSTR;
        hrow[u0] = ssum;
        for (int u = u0 + 1; u < u1; ++u) { ssum += r[u+15] - r[u-1]; hrow[u] = ssum; }
    }
    __syncthreads();

    // phase 2: b' = b - box16(b)/256 on 79x79; 79x8 units (chunks of 10 rows)
    for (int un = tid; un < 79*8; un += 512) {
        int u = un % 79, seg = un / 79;
        int v0 = seg*10, v1 = min(v0 + 10, 79);
        float ssum = 0.f;
#pragma unroll
        for (int t = 0; t < 16; ++t) ssum += hb[(v0 + t)*HSTR + u];
        for (int v = v0; v < v1; ++v) {
            if (v > v0) ssum += hb[(v+15)*HSTR + u] - hb[(v-1)*HSTR + u];
            float bp = 0.f;
            int gy = y0 - 7 + v, gx = x0 - 7 + u;
            if ((unsigned)gy < (unsigned)CROP && (unsigned)gx < (unsigned)CROP)
                bp = sb[(v+7)*BSTR + (u+7)] - ssum * (1.0f/256.0f);
            sbp[v*PSTR + u] = bp;
        }
    }
    __syncthreads();

    // phase 2.5: load a' into sa (overlays dead sb)
    for (int k = tid; k < 79*79; k += 512) {
        int i = k / 79, j = k - i*79;
        int gy = y0 - 7 + i, gx = x0 - 7 + j;
        sa[i*PSTR + j] = ((unsigned)gy < (unsigned)CROP && (unsigned)gx < (unsigned)CROP)
                         ? apc[gy*CROP + gx] : 0.f;
    }
    __syncthreads();

    float acc = 0.f;
    const float* siic = g_sii + c*CIMG;
#pragma unroll
    for (int half = 0; half < 2; ++half) {
        const int vbase = half << 5;
        // phase 3: hsum16 of b'^2, a'b' for h rows v = vbase..min(vbase+47,78)
        for (int un = tid; un < 48*8; un += 512) {
            int vr = un >> 3, ch = un & 7;
            int v = vbase + vr, q0 = ch << 3;
            if (v > 78) continue;                 // sbp has rows 0..78 only
            const float* bpr = sbp + v*PSTR;
            const float* ar  = sa  + v*PSTR;
            float s2 = 0.f, s3 = 0.f;
#pragma unroll
            for (int t = 0; t < 16; ++t) { float b_ = bpr[q0+t], a_ = ar[q0+t]; s2 += b_*b_; s3 += a_*b_; }
            float* h2r = h2 + vr*QSTR; float* h3r = h3 + vr*QSTR;
            h2r[q0] = s2; h3r[q0] = s3;
#pragma unroll
            for (int q = q0 + 1; q < q0 + 8; ++q) {
                float nb = bpr[q+15], ob = bpr[q-1];
                float na = ar[q+15],  oa = ar[q-1];
                s2 += nb*nb - ob*ob;
                s3 += na*nb - oa*ob;
                h2r[q] = s2; h3r[q] = s3;
            }
        }
        __syncthreads();

        // phase 4: vertical 16-sums -> rho for output rows p = vbase + seg*4 .. +3
        {
            int q = tid & 63, seg = tid >> 6;
            int pr0 = seg << 2;
            float s2 = 0.f, s3 = 0.f;
#pragma unroll
            for (int t = 0; t < 16; ++t) { s2 += h2[(pr0+t)*QSTR + q]; s3 += h3[(pr0+t)*QSTR + q]; }
#pragma unroll
            for (int pr = pr0; pr < pr0 + 4; ++pr) {
                if (pr > pr0) {
                    s2 += h2[(pr+15)*QSTR + q] - h2[(pr-1)*QSTR + q];
                    s3 += h3[(pr+15)*QSTR + q] - h3[(pr-1)*QSTR + q];
                }
                int gy = y0 + vbase + pr, gx = x0 + q;
                if (gy < CROP && gx < CROP) {
                    float sjj = fmaxf(s2, 1e-20f);
                    float den = sqrtf(siic[gy*CROP + gx] * sjj) + 1e-20f;
                    acc += __fdividef(s3, den);
                }
            }
        }
        __syncthreads();
    }

    // reduce 512 threads -> one double atomic
#pragma unroll
    for (int o = 16; o > 0; o >>= 1) acc += __shfl_down_sync(0xffffffffu, acc, o);
    if ((tid & 31) == 0) red[tid >> 5] = acc;
    __syncthreads();
    if (tid < 16) {
        float v = red[tid];
#pragma unroll
        for (int o = 8; o > 0; o >>= 1) v += __shfl_down_sync(0xffffu, v, o, 16);
        if (tid == 0) atomicAdd(&g_rho[z], (double)v);
    }
}

__global__ void k_argmax(int* __restrict__ out) {
    int c = threadIdx.x;
    if (c >= NCH) return;
    double best = -1e300; int bi = 0;
    for (int s = 0; s < NSHIFT; ++s) {
        double v = g_rho[s*NCH + c];
        if (v > best) { best = v; bi = s; }
    }
    out[c]       = bi / 9 - 4;
    out[NCH + c] = bi % 9 - 4;
}

extern "C" void kernel_launch(void* const* d_in, const int* in_sizes, int n_in,
                              void* d_out, int out_size) {
    const float* ms  = (const float*)d_in[0];
    const float* pan = (const float*)d_in[1];
    const float* mtf = (const float*)d_in[2];
    int* out = (int*)d_out;
    (void)in_sizes; (void)n_in; (void)out_size;

    cudaFuncSetAttribute(k_rho, cudaFuncAttributeMaxDynamicSharedMemorySize,
                         SMEM_FLOATS * (int)sizeof(float));

    k_zero<<<1, 656>>>();
    k_sepfac<<<NCH, 64>>>(mtf);
    k_gaussH<<<1024, 256>>>(pan);
    k_gaussV<<<1024, 256>>>();
    k_c13h<<<1024, 256>>>(0);
    k_c13v<<<1024, 256>>>(0);
    k_c13v<<<1024, 256>>>(1);

    dim3 mb(128), mg((CROP + 127)/128, CROP, NCH);
    k_ahsum <<<mg, mb>>>(ms);
    k_aprime<<<mg, mb>>>(ms);
    k_sqh   <<<mg, mb>>>();
    k_sii   <<<mg, mb>>>();

    k_rho<<<dim3(8, 8, NSHIFT*NCH), 512, SMEM_FLOATS * (int)sizeof(float)>>>();
    k_argmax<<<1, 32>>>(out);
}